// round 1
// baseline (speedup 1.0000x reference)
#include <cuda_runtime.h>

// IndRNN recurrent-only: h_t = relu(x_t + w * h_{t-1})
// x: [T=2048, B=64, H=512] f32, w: [H] f32, out: [T, B, H] f32
// 32768 independent chains (one per (b,h)); sequential in T only.
// Memory-bound: 256MB read + 256MB write. Strategy: 1 thread per chain,
// coalesced stride-BH loads, double-buffered unroll U=16 for deep MLP.

#define T_LEN 2048
#define B_DIM 64
#define H_DIM 512
#define NCH (B_DIM * H_DIM)   // 32768 chains
#define UNROLL 16
#define TPB 224               // 7 warps; 147 CTAs => <=1 CTA/SM, one balanced wave

__global__ __launch_bounds__(TPB, 1)
void indrnn_scan_kernel(const float* __restrict__ x,
                        const float* __restrict__ w,
                        float* __restrict__ out) {
    int idx = blockIdx.x * blockDim.x + threadIdx.x;
    if (idx >= NCH) return;

    const float wv = w[idx & (H_DIM - 1)];
    float h = 0.0f;

    const float* xp = x + idx;
    float* op = out + idx;

    float buf[UNROLL];
    float nxt[UNROLL];

    // Prologue: load first block
    #pragma unroll
    for (int u = 0; u < UNROLL; ++u)
        buf[u] = xp[(size_t)u * NCH];

    const int nblocks = T_LEN / UNROLL;
    for (int tb = 0; tb < nblocks; ++tb) {
        // Prefetch next block while computing current (MLP = UNROLL in flight)
        if (tb + 1 < nblocks) {
            const float* xn = xp + (size_t)(tb + 1) * UNROLL * NCH;
            #pragma unroll
            for (int u = 0; u < UNROLL; ++u)
                nxt[u] = xn[(size_t)u * NCH];
        }

        float* ob = op + (size_t)tb * UNROLL * NCH;
        #pragma unroll
        for (int u = 0; u < UNROLL; ++u) {
            h = fmaxf(fmaf(wv, h, buf[u]), 0.0f);
            ob[(size_t)u * NCH] = h;
        }

        #pragma unroll
        for (int u = 0; u < UNROLL; ++u)
            buf[u] = nxt[u];
    }
}

extern "C" void kernel_launch(void* const* d_in, const int* in_sizes, int n_in,
                              void* d_out, int out_size) {
    const float* x = (const float*)d_in[0];
    const float* w = (const float*)d_in[1];
    float* out = (float*)d_out;

    const int grid = (NCH + TPB - 1) / TPB;  // 147
    indrnn_scan_kernel<<<grid, TPB>>>(x, w, out);
}

// round 2
// speedup vs baseline: 1.2342x; 1.2342x over previous
#include <cuda_runtime.h>

// IndRNN recurrent-only: h_t = relu(x_t + w * h_{t-1})
// x: [T=2048, B=64, H=512] f32, w: [H] f32, out: [T, B, H] f32
// 32768 independent chains; sequential in T. Memory-bound (512MB traffic).
// R2: UNROLL 32 + ping-pong double buffer => ~4MB chip-wide MLP, no MOV copies.

#define T_LEN 2048
#define B_DIM 64
#define H_DIM 512
#define NCH (B_DIM * H_DIM)   // 32768 chains
#define UNROLL 32
#define TPB 224               // 147 CTAs -> 1 CTA/SM, single balanced wave

__global__ __launch_bounds__(TPB, 1)
void indrnn_scan_kernel(const float* __restrict__ x,
                        const float* __restrict__ w,
                        float* __restrict__ out) {
    int idx = blockIdx.x * blockDim.x + threadIdx.x;
    if (idx >= NCH) return;

    const float wv = w[idx & (H_DIM - 1)];
    float h = 0.0f;

    const float* xp = x + idx;
    float* op = out + idx;

    float bufA[UNROLL];
    float bufB[UNROLL];

    const int nblocks = T_LEN / UNROLL;  // 64 (even)

    // Prologue: load block 0 into A
    #pragma unroll
    for (int u = 0; u < UNROLL; ++u)
        bufA[u] = __ldcs(xp + (size_t)u * NCH);

    for (int tb = 0; tb < nblocks; tb += 2) {
        // Prefetch block tb+1 into B (tb+1 < nblocks always since nblocks even)
        {
            const float* xn = xp + (size_t)(tb + 1) * UNROLL * NCH;
            #pragma unroll
            for (int u = 0; u < UNROLL; ++u)
                bufB[u] = __ldcs(xn + (size_t)u * NCH);
        }

        // Compute + store block tb from A
        {
            float* ob = op + (size_t)tb * UNROLL * NCH;
            #pragma unroll
            for (int u = 0; u < UNROLL; ++u) {
                h = fmaxf(fmaf(wv, h, bufA[u]), 0.0f);
                __stcs(ob + (size_t)u * NCH, h);
            }
        }

        // Prefetch block tb+2 into A (guard last pair)
        if (tb + 2 < nblocks) {
            const float* xn = xp + (size_t)(tb + 2) * UNROLL * NCH;
            #pragma unroll
            for (int u = 0; u < UNROLL; ++u)
                bufA[u] = __ldcs(xn + (size_t)u * NCH);
        }

        // Compute + store block tb+1 from B
        {
            float* ob = op + (size_t)(tb + 1) * UNROLL * NCH;
            #pragma unroll
            for (int u = 0; u < UNROLL; ++u) {
                h = fmaxf(fmaf(wv, h, bufB[u]), 0.0f);
                __stcs(ob + (size_t)u * NCH, h);
            }
        }
    }
}

extern "C" void kernel_launch(void* const* d_in, const int* in_sizes, int n_in,
                              void* d_out, int out_size) {
    const float* x = (const float*)d_in[0];
    const float* w = (const float*)d_in[1];
    float* out = (float*)d_out;

    const int grid = (NCH + TPB - 1) / TPB;  // 147
    indrnn_scan_kernel<<<grid, TPB>>>(x, w, out);
}

// round 3
// speedup vs baseline: 1.3271x; 1.0753x over previous
#include <cuda_runtime.h>

// IndRNN recurrent-only: h_t = relu(x_t + w * h_{t-1})
// x: [T=2048, B=64, H=512] f32, w: [H] f32, out: [T,B,H] f32
// 32768 independent chains; memory-bound (512MB traffic floor).
// R3: UNROLL 64 ping-pong -> ~8MB chip-wide read MLP (reg-limited lever).

#define T_LEN 2048
#define B_DIM 64
#define H_DIM 512
#define NCH (B_DIM * H_DIM)   // 32768 chains
#define UNROLL 64
#define TPB 224               // 147 CTAs -> 1 CTA/SM, single balanced wave

__global__ __launch_bounds__(TPB, 1)
void indrnn_scan_kernel(const float* __restrict__ x,
                        const float* __restrict__ w,
                        float* __restrict__ out) {
    int idx = blockIdx.x * blockDim.x + threadIdx.x;
    if (idx >= NCH) return;

    const float wv = w[idx & (H_DIM - 1)];
    float h = 0.0f;

    const float* xp = x + idx;
    float* op = out + idx;

    float bufA[UNROLL];
    float bufB[UNROLL];

    const int nblocks = T_LEN / UNROLL;  // 32 (even)

    // Prologue: load block 0 into A
    #pragma unroll
    for (int u = 0; u < UNROLL; ++u)
        bufA[u] = __ldcs(xp + (size_t)u * NCH);

    for (int tb = 0; tb < nblocks; tb += 2) {
        // Prefetch block tb+1 into B
        {
            const float* xn = xp + (size_t)(tb + 1) * UNROLL * NCH;
            #pragma unroll
            for (int u = 0; u < UNROLL; ++u)
                bufB[u] = __ldcs(xn + (size_t)u * NCH);
        }

        // Compute + store block tb from A
        {
            float* ob = op + (size_t)tb * UNROLL * NCH;
            #pragma unroll
            for (int u = 0; u < UNROLL; ++u) {
                h = fmaxf(fmaf(wv, h, bufA[u]), 0.0f);
                __stcs(ob + (size_t)u * NCH, h);
            }
        }

        // Prefetch block tb+2 into A (skip on last pair)
        if (tb + 2 < nblocks) {
            const float* xn = xp + (size_t)(tb + 2) * UNROLL * NCH;
            #pragma unroll
            for (int u = 0; u < UNROLL; ++u)
                bufA[u] = __ldcs(xn + (size_t)u * NCH);
        }

        // Compute + store block tb+1 from B
        {
            float* ob = op + (size_t)(tb + 1) * UNROLL * NCH;
            #pragma unroll
            for (int u = 0; u < UNROLL; ++u) {
                h = fmaxf(fmaf(wv, h, bufB[u]), 0.0f);
                __stcs(ob + (size_t)u * NCH, h);
            }
        }
    }
}

extern "C" void kernel_launch(void* const* d_in, const int* in_sizes, int n_in,
                              void* d_out, int out_size) {
    const float* x = (const float*)d_in[0];
    const float* w = (const float*)d_in[1];
    float* out = (float*)d_out;

    const int grid = (NCH + TPB - 1) / TPB;  // 147
    indrnn_scan_kernel<<<grid, TPB>>>(x, w, out);
}